// round 13
// baseline (speedup 1.0000x reference)
#include <cuda_runtime.h>
#include <cuda_bf16.h>
#include <cstdint>

// B=8, T=4096, D=512, DI=1024, K=7; BT=32768 rows.
// GEMMs: bf16 mma.sync m16n8k16 + ldmatrix, BK=64, SW128 swizzle, 3-stage cp.async.

// ---------------------------------------------------------------------------
// Scratch (bytes).
#define OB_XP  0ull            // x_proj bf16    32768 x 1024
#define OB_Z   67108864ull     // z bf16         32768 x 1024
#define OB_CF  134217728ull    // conv fwd bf16
#define OB_CB  201326592ull    // conv bwd bf16
#define OB_YF  268435456ull    // silu(proj_f) bf16
#define OB_Y2  335544320ull    // gated y bf16
#define OB_XB  402653184ull    // x bf16         32768 x 512
#define OB_WIB 436207616ull    // in_proj_w bf16 2048 x 512
#define OB_PFB 438304768ull    // proj_fwd_w bf16 1024x1024
#define OB_PBB 440401920ull    // proj_bwd_w bf16
#define OB_OWB 442499072ull    // out_proj_w bf16 512x1024
#define OB_H   443547648ull    // h fp32         32768 x 512
#define SCRATCH_BYTES 510656512ull

__device__ __align__(256) unsigned char g_scratch[SCRATCH_BYTES];

__device__ __forceinline__ float siluf(float v) { return v / (1.0f + expf(-v)); }

__device__ __forceinline__ uint32_t smem_u32(const void* p) {
    uint32_t a;
    asm("{ .reg .u64 t; cvta.to.shared.u64 t, %1; cvt.u32.u64 %0, t; }" : "=r"(a) : "l"(p));
    return a;
}

#define CP16(dst, src) \
    asm volatile("cp.async.cg.shared.global [%0], [%1], 16;" :: "r"(dst), "l"(src))
#define CPCOMMIT() asm volatile("cp.async.commit_group;" ::: "memory")

__device__ __forceinline__ void mma_bf16(float& c0, float& c1, float& c2, float& c3,
                                         uint32_t a0, uint32_t a1, uint32_t a2, uint32_t a3,
                                         uint32_t b0, uint32_t b1) {
    asm volatile(
        "mma.sync.aligned.m16n8k16.row.col.f32.bf16.bf16.f32 "
        "{%0,%1,%2,%3}, {%4,%5,%6,%7}, {%8,%9}, {%0,%1,%2,%3};"
        : "+f"(c0), "+f"(c1), "+f"(c2), "+f"(c3)
        : "r"(a0), "r"(a1), "r"(a2), "r"(a3), "r"(b0), "r"(b1));
}

__device__ __forceinline__ void ldsm4(uint32_t& r0, uint32_t& r1, uint32_t& r2, uint32_t& r3,
                                      uint32_t addr) {
    asm volatile("ldmatrix.sync.aligned.m8n8.x4.shared.b16 {%0,%1,%2,%3}, [%4];"
                 : "=r"(r0), "=r"(r1), "=r"(r2), "=r"(r3) : "r"(addr));
}

// ---------------------------------------------------------------------------
// bf16 TN GEMM: C[m,n] = sum_k A[m,k]*B[n,k]. Tile 128x128, BK=64, 256 thr,
// 3-stage cp.async ring (stage = 32KB: A 16KB + B 16KB), SW128 swizzle:
//   off(row,k) = row*128 + (((k>>3) ^ (row&7))*16) + (k&7)*2
// mode 0: split store bf16: col<1024 -> Cv (XP), else -> C2 (Z), stride 1024
// mode 1: +bias[n]; t==0    ? 0 : silu -> bf16  (fwd mixer)
// mode 4: +bias[n]; t==4095 ? 0 : silu = yb; y=(yb+yf+xp*dw)*silu(z)*gs -> bf16
// mode 3: +res[m,n] -> fp32
__global__ __launch_bounds__(256)
void gemm_mma(const __nv_bfloat16* __restrict__ A, const __nv_bfloat16* __restrict__ B,
              void* __restrict__ Cv, void* __restrict__ C2,
              int M, int N, int K, int mode,
              const float* __restrict__ bias, const float* __restrict__ res,
              const __nv_bfloat16* __restrict__ YF, const __nv_bfloat16* __restrict__ XP,
              const __nv_bfloat16* __restrict__ ZB, const float* __restrict__ dw,
              const float* __restrict__ gsp)
{
    extern __shared__ __align__(128) unsigned char dsm[];
    // stage s (0..2): A at s*32768, B at s*32768+16384

    const int tid = threadIdx.x;
    const int wid = tid >> 5, lane = tid & 31;
    const int g = lane >> 2, t = lane & 3;
    const int wm = wid >> 2, wn = wid & 3;         // 2 x 4 warp grid
    const int mBase = wm * 64, nBase = wn * 32;    // 64x32 warp tile
    const int bn = blockIdx.x, bm = blockIdx.y;

    const __nv_bfloat16* Ab = A + (size_t)bm * 128 * K;
    const __nv_bfloat16* Bb = B + (size_t)bn * 128 * K;

    const uint32_t sbase = smem_u32(dsm);

    // loader: 1024 uint4 per matrix per chunk, 4 per thread
    int lrow[4]; uint32_t ldst[4];
    #pragma unroll
    for (int i = 0; i < 4; i++) {
        int idx = tid + i * 256;
        int row = idx >> 3, cu = idx & 7;
        lrow[i] = row;
        ldst[i] = (uint32_t)(row * 128 + ((cu ^ (row & 7)) << 4));
    }
    const int lcu = tid & 7;  // source k-unit (8 bf16)

    // ldmatrix per-lane geometry
    const int arow_l = (lane & 15);
    const int akk_l  = (lane >> 4);            // in 8-elem units
    const int brow_l = (lane & 7) + ((lane >> 4) << 3);
    const int bkk_l  = ((lane >> 3) & 1);

    float acc[4][4][4];
    #pragma unroll
    for (int i = 0; i < 4; i++)
        #pragma unroll
        for (int j = 0; j < 4; j++)
            #pragma unroll
            for (int q = 0; q < 4; q++) acc[i][j][q] = 0.0f;

    const int nch = K >> 6;

    // prologue: chunks 0,1 -> stages 0,1
    #pragma unroll
    for (int i = 0; i < 4; i++) {
        CP16(sbase + ldst[i],         Ab + (size_t)lrow[i] * K + lcu * 8);
        CP16(sbase + 16384 + ldst[i], Bb + (size_t)lrow[i] * K + lcu * 8);
    }
    CPCOMMIT();
    if (nch > 1) {
        #pragma unroll
        for (int i = 0; i < 4; i++) {
            CP16(sbase + 32768 + ldst[i],         Ab + (size_t)lrow[i] * K + 64 + lcu * 8);
            CP16(sbase + 32768 + 16384 + ldst[i], Bb + (size_t)lrow[i] * K + 64 + lcu * 8);
        }
    }
    CPCOMMIT();

    int st = 0;        // stage holding chunk ch
    int st2 = 2;       // stage for chunk ch+2
    for (int ch = 0; ch < nch; ch++) {
        if (ch + 2 < nch) {
            const int k0 = (ch + 2) << 6;
            const uint32_t nb = (uint32_t)st2 * 32768u;
            #pragma unroll
            for (int i = 0; i < 4; i++) {
                CP16(sbase + nb + ldst[i],         Ab + (size_t)lrow[i] * K + k0 + lcu * 8);
                CP16(sbase + nb + 16384 + ldst[i], Bb + (size_t)lrow[i] * K + k0 + lcu * 8);
            }
            CPCOMMIT();
            asm volatile("cp.async.wait_group %0;" :: "n"(2) : "memory");
        } else if (ch + 1 < nch) {
            asm volatile("cp.async.wait_group %0;" :: "n"(1) : "memory");
        } else {
            asm volatile("cp.async.wait_group %0;" :: "n"(0) : "memory");
        }
        __syncthreads();

        const uint32_t pa = sbase + (uint32_t)st * 32768u;
        const uint32_t pb = pa + 16384u;

        #pragma unroll
        for (int ks = 0; ks < 4; ks++) {
            uint32_t af[4][4];
            #pragma unroll
            for (int mf = 0; mf < 4; mf++) {
                int row = mBase + mf * 16 + arow_l;
                int kk = ks * 2 + akk_l;
                uint32_t off = (uint32_t)(row * 128 + ((kk ^ (row & 7)) << 4));
                ldsm4(af[mf][0], af[mf][1], af[mf][2], af[mf][3], pa + off);
            }
            uint32_t bf[4][2];
            #pragma unroll
            for (int p = 0; p < 2; p++) {
                int row = nBase + p * 16 + brow_l;
                int kk = ks * 2 + bkk_l;
                uint32_t off = (uint32_t)(row * 128 + ((kk ^ (row & 7)) << 4));
                ldsm4(bf[p * 2][0], bf[p * 2][1], bf[p * 2 + 1][0], bf[p * 2 + 1][1], pb + off);
            }
            #pragma unroll
            for (int mf = 0; mf < 4; mf++)
                #pragma unroll
                for (int nf = 0; nf < 4; nf++)
                    mma_bf16(acc[mf][nf][0], acc[mf][nf][1], acc[mf][nf][2], acc[mf][nf][3],
                             af[mf][0], af[mf][1], af[mf][2], af[mf][3],
                             bf[nf][0], bf[nf][1]);
        }
        __syncthreads();
        st  = (st  == 2) ? 0 : st  + 1;
        st2 = (st2 == 2) ? 0 : st2 + 1;
    }

    // Epilogue. c0,c1: row g, cols t*2,t*2+1 ; c2,c3: row g+8.
    const float gsv = (mode == 4) ? gsp[0] : 0.0f;
    #pragma unroll
    for (int mf = 0; mf < 4; mf++) {
        #pragma unroll
        for (int half = 0; half < 2; half++) {
            size_t m = (size_t)bm * 128 + mBase + mf * 16 + g + half * 8;
            int tt = (int)(m & 4095);
            #pragma unroll
            for (int nf = 0; nf < 4; nf++) {
                int col = bn * 128 + nBase + nf * 8 + t * 2;
                float v0 = acc[mf][nf][half * 2 + 0];
                float v1 = acc[mf][nf][half * 2 + 1];
                if (mode == 0) {
                    __nv_bfloat162 o = __floats2bfloat162_rn(v0, v1);
                    if (col < 1024)
                        *(__nv_bfloat162*)((__nv_bfloat16*)Cv + m * 1024 + col) = o;
                    else
                        *(__nv_bfloat162*)((__nv_bfloat16*)C2 + m * 1024 + (col - 1024)) = o;
                } else if (mode == 1) {
                    v0 += bias[col]; v1 += bias[col + 1];
                    if (tt == 0) { v0 = 0.0f; v1 = 0.0f; }
                    else { v0 = siluf(v0); v1 = siluf(v1); }
                    *(__nv_bfloat162*)((__nv_bfloat16*)Cv + m * (size_t)N + col) =
                        __floats2bfloat162_rn(v0, v1);
                } else if (mode == 4) {
                    v0 += bias[col]; v1 += bias[col + 1];
                    if (tt == 4095) { v0 = 0.0f; v1 = 0.0f; }
                    else { v0 = siluf(v0); v1 = siluf(v1); }
                    __nv_bfloat162 yf2 = *(const __nv_bfloat162*)(YF + m * 1024 + col);
                    __nv_bfloat162 xp2 = *(const __nv_bfloat162*)(XP + m * 1024 + col);
                    __nv_bfloat162 z2  = *(const __nv_bfloat162*)(ZB + m * 1024 + col);
                    float y0 = (v0 + __bfloat162float(yf2.x)
                                + __bfloat162float(xp2.x) * dw[col])
                               * siluf(__bfloat162float(z2.x)) * gsv;
                    float y1 = (v1 + __bfloat162float(yf2.y)
                                + __bfloat162float(xp2.y) * dw[col + 1])
                               * siluf(__bfloat162float(z2.y)) * gsv;
                    *(__nv_bfloat162*)((__nv_bfloat16*)Cv + m * (size_t)N + col) =
                        __floats2bfloat162_rn(y0, y1);
                } else { // mode 3
                    v0 += res[m * (size_t)N + col];
                    v1 += res[m * (size_t)N + col + 1];
                    float2 o; o.x = v0; o.y = v1;
                    *(float2*)((float*)Cv + m * (size_t)N + col) = o;
                }
            }
        }
    }
}

// ---------------------------------------------------------------------------
// fp32 -> bf16 convert
__global__ void to_bf16(const float4* __restrict__ s, uint2* __restrict__ d)
{
    int i = blockIdx.x * 256 + threadIdx.x;
    float4 v = s[i];
    __nv_bfloat162 a = __floats2bfloat162_rn(v.x, v.y);
    __nv_bfloat162 b = __floats2bfloat162_rn(v.z, v.w);
    uint2 o;
    o.x = *reinterpret_cast<uint32_t*>(&a);
    o.y = *reinterpret_cast<uint32_t*>(&b);
    d[i] = o;
}

// ---------------------------------------------------------------------------
// Depthwise convs, shifts baked in. 2 channels per thread (bf16x2).
__global__ void conv_kernel(const __nv_bfloat16* __restrict__ xp0,
    const float* __restrict__ wf, const float* __restrict__ bf,
    const float* __restrict__ wb, const float* __restrict__ bb,
    __nv_bfloat16* __restrict__ cf, __nv_bfloat16* __restrict__ cb)
{
    int idx = blockIdx.x * 256 + threadIdx.x;   // pair index < 32768*512
    int cp = idx & 511;
    int bt = idx >> 9;
    int t = bt & 4095;
    int c = cp * 2;
    const uint32_t* xp = (const uint32_t*)(xp0 + (size_t)(bt - t) * 1024) + cp;

    float w0f[7], w1f[7], w0b[7], w1b[7];
    #pragma unroll
    for (int k = 0; k < 7; k++) {
        w0f[k] = wf[c * 7 + k];       w1f[k] = wf[(c + 1) * 7 + k];
        w0b[k] = wb[c * 7 + k];       w1b[k] = wb[(c + 1) * 7 + k];
    }
    float sf0 = bf[c], sf1 = bf[c + 1];
    float sb0 = bb[c], sb1 = bb[c + 1];
    #pragma unroll
    for (int k = 0; k < 7; k++) {
        int tf = t - 7 + k;
        if (tf >= 0) {
            uint32_t u = xp[(size_t)tf * 512];
            __nv_bfloat162 v = *reinterpret_cast<__nv_bfloat162*>(&u);
            sf0 += __bfloat162float(v.x) * w0f[k];
            sf1 += __bfloat162float(v.y) * w1f[k];
        }
        int tb = t + 7 - k;
        if (tb < 4096) {
            uint32_t u = xp[(size_t)tb * 512];
            __nv_bfloat162 v = *reinterpret_cast<__nv_bfloat162*>(&u);
            sb0 += __bfloat162float(v.x) * w0b[k];
            sb1 += __bfloat162float(v.y) * w1b[k];
        }
    }
    ((__nv_bfloat162*)cf)[idx] = __floats2bfloat162_rn(sf0, sf1);
    ((__nv_bfloat162*)cb)[idx] = __floats2bfloat162_rn(sb0, sb1);
}

// ---------------------------------------------------------------------------
// LayerNorm over D=512 per row (fp32 in/out).
__global__ void ln_kernel(const float* __restrict__ h,
    const float* __restrict__ g, const float* __restrict__ b,
    float* __restrict__ out)
{
    __shared__ float a1[4], a2[4];
    int row = blockIdx.x;
    int tid = threadIdx.x;  // 128
    const float4 v = ((const float4*)(h + (size_t)row * 512))[tid];
    float s1 = v.x + v.y + v.z + v.w;
    float s2 = v.x * v.x + v.y * v.y + v.z * v.z + v.w * v.w;
    #pragma unroll
    for (int o = 16; o; o >>= 1) {
        s1 += __shfl_xor_sync(0xffffffffu, s1, o);
        s2 += __shfl_xor_sync(0xffffffffu, s2, o);
    }
    if ((tid & 31) == 0) { a1[tid >> 5] = s1; a2[tid >> 5] = s2; }
    __syncthreads();
    s1 = a1[0] + a1[1] + a1[2] + a1[3];
    s2 = a2[0] + a2[1] + a2[2] + a2[3];
    float mu  = s1 * (1.0f / 512.0f);
    float var = s2 * (1.0f / 512.0f) - mu * mu;
    float inv = rsqrtf(var + 1e-5f);
    float4 gg = ((const float4*)g)[tid];
    float4 bb = ((const float4*)b)[tid];
    float4 o;
    o.x = (v.x - mu) * inv * gg.x + bb.x;
    o.y = (v.y - mu) * inv * gg.y + bb.y;
    o.z = (v.z - mu) * inv * gg.z + bb.z;
    o.w = (v.w - mu) * inv * gg.w + bb.w;
    ((float4*)(out + (size_t)row * 512))[tid] = o;
}

// ---------------------------------------------------------------------------
extern "C" void kernel_launch(void* const* d_in, const int* in_sizes, int n_in,
                              void* d_out, int out_size)
{
    (void)in_sizes; (void)n_in; (void)out_size;
    const float* x   = (const float*)d_in[0];
    const float* wi  = (const float*)d_in[1];
    const float* cfw = (const float*)d_in[2];
    const float* cfb = (const float*)d_in[3];
    const float* pfw = (const float*)d_in[4];
    const float* pfb = (const float*)d_in[5];
    const float* cbw = (const float*)d_in[6];
    const float* cbb = (const float*)d_in[7];
    const float* pbw = (const float*)d_in[8];
    const float* pbb = (const float*)d_in[9];
    const float* dw  = (const float*)d_in[10];
    const float* gs  = (const float*)d_in[11];
    const float* ow  = (const float*)d_in[12];
    const float* lng = (const float*)d_in[13];
    const float* lnb = (const float*)d_in[14];
    float* out = (float*)d_out;

    unsigned char* S = nullptr;
    cudaGetSymbolAddress((void**)&S, g_scratch);

    __nv_bfloat16* XP  = (__nv_bfloat16*)(S + OB_XP);
    __nv_bfloat16* ZB  = (__nv_bfloat16*)(S + OB_Z);
    __nv_bfloat16* CF  = (__nv_bfloat16*)(S + OB_CF);
    __nv_bfloat16* CB  = (__nv_bfloat16*)(S + OB_CB);
    __nv_bfloat16* YF  = (__nv_bfloat16*)(S + OB_YF);
    __nv_bfloat16* Y2  = (__nv_bfloat16*)(S + OB_Y2);
    __nv_bfloat16* XB  = (__nv_bfloat16*)(S + OB_XB);
    __nv_bfloat16* WIB = (__nv_bfloat16*)(S + OB_WIB);
    __nv_bfloat16* PFB = (__nv_bfloat16*)(S + OB_PFB);
    __nv_bfloat16* PBB = (__nv_bfloat16*)(S + OB_PBB);
    __nv_bfloat16* OWB = (__nv_bfloat16*)(S + OB_OWB);
    float*         H   = (float*)(S + OB_H);

    cudaFuncSetAttribute(gemm_mma, cudaFuncAttributeMaxDynamicSharedMemorySize, 98304);
    const int SMEM = 98304;

    // 0) fp32 -> bf16 staging
    to_bf16<<<16384, 256>>>((const float4*)x,   (uint2*)XB);   // 32768x512
    to_bf16<<<1024, 256>>>((const float4*)wi,   (uint2*)WIB);  // 2048x512
    to_bf16<<<1024, 256>>>((const float4*)pfw,  (uint2*)PFB);  // 1024x1024
    to_bf16<<<1024, 256>>>((const float4*)pbw,  (uint2*)PBB);  // 1024x1024
    to_bf16<<<512,  256>>>((const float4*)ow,   (uint2*)OWB);  // 512x1024

    // 1) xz = x @ in_proj_w^T  -> split XP | Z (bf16)
    gemm_mma<<<dim3(16, 256), 256, SMEM>>>(XB, WIB, XP, ZB, 32768, 2048, 512, 0,
        nullptr, nullptr, nullptr, nullptr, nullptr, nullptr, nullptr);

    // 2) depthwise convs (shift/flip folded) -> bf16
    conv_kernel<<<(32768 * 512) / 256, 256>>>(XP, cfw, cfb, cbw, cbb, CF, CB);

    // 3a) fwd mixer: silu(cf @ Wf^T + b), t==0 masked -> YF
    gemm_mma<<<dim3(8, 256), 256, SMEM>>>(CF, PFB, YF, nullptr, 32768, 1024, 1024, 1,
        pfb, nullptr, nullptr, nullptr, nullptr, nullptr, nullptr);

    // 3b) bwd mixer fused with combine -> Y2
    gemm_mma<<<dim3(8, 256), 256, SMEM>>>(CB, PBB, Y2, nullptr, 32768, 1024, 1024, 4,
        pbb, nullptr, YF, XP, ZB, dw, gs);

    // 4) out_proj + residual -> fp32 H
    gemm_mma<<<dim3(4, 256), 256, SMEM>>>(Y2, OWB, H, nullptr, 32768, 512, 1024, 3,
        nullptr, x, nullptr, nullptr, nullptr, nullptr, nullptr);

    // 5) LayerNorm
    ln_kernel<<<32768, 128>>>(H, lng, lnb, out);
}

// round 16
// speedup vs baseline: 1.5210x; 1.5210x over previous
#include <cuda_runtime.h>
#include <cuda_bf16.h>
#include <cstdint>

// B=8, T=4096, D=512, DI=1024, K=7; BT=32768 rows.
// GEMMs: bf16 mma.sync m16n8k16 + ldmatrix, BK=64, SW128 swizzle,
// 2-stage cp.async (64KB smem -> 3 CTAs/SM).

// ---------------------------------------------------------------------------
// Scratch (bytes).
#define OB_XP  0ull            // x_proj bf16    32768 x 1024
#define OB_Z   67108864ull     // z bf16         32768 x 1024
#define OB_CF  134217728ull    // conv fwd bf16
#define OB_CB  201326592ull    // conv bwd bf16
#define OB_YF  268435456ull    // silu(proj_f) bf16
#define OB_Y2  335544320ull    // gated y bf16
#define OB_XB  402653184ull    // x bf16         32768 x 512
#define OB_WIB 436207616ull    // in_proj_w bf16 2048 x 512
#define OB_PFB 438304768ull    // proj_fwd_w bf16 1024x1024
#define OB_PBB 440401920ull    // proj_bwd_w bf16
#define OB_OWB 442499072ull    // out_proj_w bf16 512x1024
#define OB_H   443547648ull    // h fp32         32768 x 512
#define SCRATCH_BYTES 510656512ull

__device__ __align__(256) unsigned char g_scratch[SCRATCH_BYTES];

__device__ __forceinline__ float siluf(float v) { return v / (1.0f + expf(-v)); }

__device__ __forceinline__ uint32_t smem_u32(const void* p) {
    uint32_t a;
    asm("{ .reg .u64 t; cvta.to.shared.u64 t, %1; cvt.u32.u64 %0, t; }" : "=r"(a) : "l"(p));
    return a;
}

#define CP16(dst, src) \
    asm volatile("cp.async.cg.shared.global [%0], [%1], 16;" :: "r"(dst), "l"(src))
#define CPCOMMIT() asm volatile("cp.async.commit_group;" ::: "memory")

__device__ __forceinline__ void mma_bf16(float& c0, float& c1, float& c2, float& c3,
                                         uint32_t a0, uint32_t a1, uint32_t a2, uint32_t a3,
                                         uint32_t b0, uint32_t b1) {
    asm volatile(
        "mma.sync.aligned.m16n8k16.row.col.f32.bf16.bf16.f32 "
        "{%0,%1,%2,%3}, {%4,%5,%6,%7}, {%8,%9}, {%0,%1,%2,%3};"
        : "+f"(c0), "+f"(c1), "+f"(c2), "+f"(c3)
        : "r"(a0), "r"(a1), "r"(a2), "r"(a3), "r"(b0), "r"(b1));
}

__device__ __forceinline__ void ldsm4(uint32_t& r0, uint32_t& r1, uint32_t& r2, uint32_t& r3,
                                      uint32_t addr) {
    asm volatile("ldmatrix.sync.aligned.m8n8.x4.shared.b16 {%0,%1,%2,%3}, [%4];"
                 : "=r"(r0), "=r"(r1), "=r"(r2), "=r"(r3) : "r"(addr));
}

// ---------------------------------------------------------------------------
// bf16 TN GEMM: C[m,n] = sum_k A[m,k]*B[n,k]. Tile 128x128, BK=64, 256 thr.
// Tiles stored as 128 rows x 128B (64 bf16), SW128 swizzle:
//   off(row,k) = row*128 + (((k>>3) ^ (row&7))*16) + (k&7)*2
// mode 0: split store bf16: col<1024 -> C (XP), else -> C2 (Z), stride 1024
// mode 1: +bias[n]; t==0    ? 0 : silu -> bf16  (fwd mixer)
// mode 4: +bias[n]; t==4095 ? 0 : silu = yb; y=(yb+yf+xp*dw)*silu(z)*gs -> bf16
// mode 3: +res[m,n] -> fp32
__global__ __launch_bounds__(256)
void gemm_mma(const __nv_bfloat16* __restrict__ A, const __nv_bfloat16* __restrict__ B,
              void* __restrict__ Cv, void* __restrict__ C2,
              int M, int N, int K, int mode,
              const float* __restrict__ bias, const float* __restrict__ res,
              const __nv_bfloat16* __restrict__ YF, const __nv_bfloat16* __restrict__ XP,
              const __nv_bfloat16* __restrict__ ZB, const float* __restrict__ dw,
              const float* __restrict__ gsp)
{
    extern __shared__ __align__(128) unsigned char dsm[];
    // layout: buf s (s=0,1): A at s*32768, B at s*32768+16384

    const int tid = threadIdx.x;
    const int wid = tid >> 5, lane = tid & 31;
    const int g = lane >> 2, t = lane & 3;
    const int wm = wid >> 2, wn = wid & 3;         // 2 x 4 warp grid
    const int mBase = wm * 64, nBase = wn * 32;    // 64x32 warp tile
    const int bn = blockIdx.x, bm = blockIdx.y;

    const __nv_bfloat16* Ab = A + (size_t)bm * 128 * K;
    const __nv_bfloat16* Bb = B + (size_t)bn * 128 * K;

    const uint32_t sbase = smem_u32(dsm);

    // loader: 1024 uint4 per matrix per chunk, 4 per thread
    int lrow[4]; uint32_t ldst[4];
    #pragma unroll
    for (int i = 0; i < 4; i++) {
        int idx = tid + i * 256;
        int row = idx >> 3, cu = idx & 7;
        lrow[i] = row;
        ldst[i] = (uint32_t)(row * 128 + ((cu ^ (row & 7)) << 4));
    }
    const int lcu = tid & 7;  // source k-unit (8 bf16)

    // ldmatrix per-lane geometry
    const int arow_l = (lane & 15);
    const int akk_l  = (lane >> 4);            // in 8-elem units
    const int brow_l = (lane & 7) + ((lane >> 4) << 3);
    const int bkk_l  = ((lane >> 3) & 1);

    float acc[4][4][4];
    #pragma unroll
    for (int i = 0; i < 4; i++)
        #pragma unroll
        for (int j = 0; j < 4; j++)
            #pragma unroll
            for (int q = 0; q < 4; q++) acc[i][j][q] = 0.0f;

    const int nch = K >> 6;

    // prologue: chunk 0 -> buf 0
    #pragma unroll
    for (int i = 0; i < 4; i++) {
        CP16(sbase + ldst[i],         Ab + (size_t)lrow[i] * K + lcu * 8);
        CP16(sbase + 16384 + ldst[i], Bb + (size_t)lrow[i] * K + lcu * 8);
    }
    CPCOMMIT();

    for (int ch = 0; ch < nch; ch++) {
        if (ch + 1 < nch) {
            const int k0 = (ch + 1) << 6;
            const uint32_t nb = (uint32_t)((ch + 1) & 1) * 32768u;
            #pragma unroll
            for (int i = 0; i < 4; i++) {
                CP16(sbase + nb + ldst[i],         Ab + (size_t)lrow[i] * K + k0 + lcu * 8);
                CP16(sbase + nb + 16384 + ldst[i], Bb + (size_t)lrow[i] * K + k0 + lcu * 8);
            }
            CPCOMMIT();
            asm volatile("cp.async.wait_group %0;" :: "n"(1) : "memory");
        } else {
            asm volatile("cp.async.wait_group %0;" :: "n"(0) : "memory");
        }
        __syncthreads();

        const uint32_t pa = sbase + (uint32_t)(ch & 1) * 32768u;
        const uint32_t pb = pa + 16384u;

        #pragma unroll
        for (int ks = 0; ks < 4; ks++) {
            uint32_t af[4][4];
            #pragma unroll
            for (int mf = 0; mf < 4; mf++) {
                int row = mBase + mf * 16 + arow_l;
                int kk = ks * 2 + akk_l;
                uint32_t off = (uint32_t)(row * 128 + ((kk ^ (row & 7)) << 4));
                ldsm4(af[mf][0], af[mf][1], af[mf][2], af[mf][3], pa + off);
            }
            uint32_t bf[4][2];
            #pragma unroll
            for (int p = 0; p < 2; p++) {
                int row = nBase + p * 16 + brow_l;
                int kk = ks * 2 + bkk_l;
                uint32_t off = (uint32_t)(row * 128 + ((kk ^ (row & 7)) << 4));
                ldsm4(bf[p * 2][0], bf[p * 2][1], bf[p * 2 + 1][0], bf[p * 2 + 1][1], pb + off);
            }
            #pragma unroll
            for (int mf = 0; mf < 4; mf++)
                #pragma unroll
                for (int nf = 0; nf < 4; nf++)
                    mma_bf16(acc[mf][nf][0], acc[mf][nf][1], acc[mf][nf][2], acc[mf][nf][3],
                             af[mf][0], af[mf][1], af[mf][2], af[mf][3],
                             bf[nf][0], bf[nf][1]);
        }
        __syncthreads();
    }

    // Epilogue. c0,c1: row g, cols t*2,t*2+1 ; c2,c3: row g+8.
    const float gsv = (mode == 4) ? gsp[0] : 0.0f;
    #pragma unroll
    for (int mf = 0; mf < 4; mf++) {
        #pragma unroll
        for (int half = 0; half < 2; half++) {
            size_t m = (size_t)bm * 128 + mBase + mf * 16 + g + half * 8;
            int tt = (int)(m & 4095);
            #pragma unroll
            for (int nf = 0; nf < 4; nf++) {
                int col = bn * 128 + nBase + nf * 8 + t * 2;
                float v0 = acc[mf][nf][half * 2 + 0];
                float v1 = acc[mf][nf][half * 2 + 1];
                if (mode == 0) {
                    __nv_bfloat162 o = __floats2bfloat162_rn(v0, v1);
                    if (col < 1024)
                        *(__nv_bfloat162*)((__nv_bfloat16*)Cv + m * 1024 + col) = o;
                    else
                        *(__nv_bfloat162*)((__nv_bfloat16*)C2 + m * 1024 + (col - 1024)) = o;
                } else if (mode == 1) {
                    v0 += bias[col]; v1 += bias[col + 1];
                    if (tt == 0) { v0 = 0.0f; v1 = 0.0f; }
                    else { v0 = siluf(v0); v1 = siluf(v1); }
                    *(__nv_bfloat162*)((__nv_bfloat16*)Cv + m * (size_t)N + col) =
                        __floats2bfloat162_rn(v0, v1);
                } else if (mode == 4) {
                    v0 += bias[col]; v1 += bias[col + 1];
                    if (tt == 4095) { v0 = 0.0f; v1 = 0.0f; }
                    else { v0 = siluf(v0); v1 = siluf(v1); }
                    __nv_bfloat162 yf2 = *(const __nv_bfloat162*)(YF + m * 1024 + col);
                    __nv_bfloat162 xp2 = *(const __nv_bfloat162*)(XP + m * 1024 + col);
                    __nv_bfloat162 z2  = *(const __nv_bfloat162*)(ZB + m * 1024 + col);
                    float y0 = (v0 + __bfloat162float(yf2.x)
                                + __bfloat162float(xp2.x) * dw[col])
                               * siluf(__bfloat162float(z2.x)) * gsv;
                    float y1 = (v1 + __bfloat162float(yf2.y)
                                + __bfloat162float(xp2.y) * dw[col + 1])
                               * siluf(__bfloat162float(z2.y)) * gsv;
                    *(__nv_bfloat162*)((__nv_bfloat16*)Cv + m * (size_t)N + col) =
                        __floats2bfloat162_rn(y0, y1);
                } else { // mode 3
                    v0 += res[m * (size_t)N + col];
                    v1 += res[m * (size_t)N + col + 1];
                    float2 o; o.x = v0; o.y = v1;
                    *(float2*)((float*)Cv + m * (size_t)N + col) = o;
                }
            }
        }
    }
}

// ---------------------------------------------------------------------------
// fp32 -> bf16 convert
__global__ void to_bf16(const float4* __restrict__ s, uint2* __restrict__ d)
{
    int i = blockIdx.x * 256 + threadIdx.x;
    float4 v = s[i];
    __nv_bfloat162 a = __floats2bfloat162_rn(v.x, v.y);
    __nv_bfloat162 b = __floats2bfloat162_rn(v.z, v.w);
    uint2 o;
    o.x = *reinterpret_cast<uint32_t*>(&a);
    o.y = *reinterpret_cast<uint32_t*>(&b);
    d[i] = o;
}

// ---------------------------------------------------------------------------
// Depthwise convs, shifts baked in. 2 channels per thread (bf16x2).
__global__ void conv_kernel(const __nv_bfloat16* __restrict__ xp0,
    const float* __restrict__ wf, const float* __restrict__ bf,
    const float* __restrict__ wb, const float* __restrict__ bb,
    __nv_bfloat16* __restrict__ cf, __nv_bfloat16* __restrict__ cb)
{
    int idx = blockIdx.x * 256 + threadIdx.x;   // pair index < 32768*512
    int cp = idx & 511;
    int bt = idx >> 9;
    int t = bt & 4095;
    int c = cp * 2;
    const uint32_t* xp = (const uint32_t*)(xp0 + (size_t)(bt - t) * 1024) + cp;

    float w0f[7], w1f[7], w0b[7], w1b[7];
    #pragma unroll
    for (int k = 0; k < 7; k++) {
        w0f[k] = wf[c * 7 + k];       w1f[k] = wf[(c + 1) * 7 + k];
        w0b[k] = wb[c * 7 + k];       w1b[k] = wb[(c + 1) * 7 + k];
    }
    float sf0 = bf[c], sf1 = bf[c + 1];
    float sb0 = bb[c], sb1 = bb[c + 1];
    #pragma unroll
    for (int k = 0; k < 7; k++) {
        int tf = t - 7 + k;
        if (tf >= 0) {
            uint32_t u = xp[(size_t)tf * 512];
            __nv_bfloat162 v = *reinterpret_cast<__nv_bfloat162*>(&u);
            sf0 += __bfloat162float(v.x) * w0f[k];
            sf1 += __bfloat162float(v.y) * w1f[k];
        }
        int tb = t + 7 - k;
        if (tb < 4096) {
            uint32_t u = xp[(size_t)tb * 512];
            __nv_bfloat162 v = *reinterpret_cast<__nv_bfloat162*>(&u);
            sb0 += __bfloat162float(v.x) * w0b[k];
            sb1 += __bfloat162float(v.y) * w1b[k];
        }
    }
    ((__nv_bfloat162*)cf)[idx] = __floats2bfloat162_rn(sf0, sf1);
    ((__nv_bfloat162*)cb)[idx] = __floats2bfloat162_rn(sb0, sb1);
}

// ---------------------------------------------------------------------------
// LayerNorm over D=512 per row (fp32 in/out).
__global__ void ln_kernel(const float* __restrict__ h,
    const float* __restrict__ g, const float* __restrict__ b,
    float* __restrict__ out)
{
    __shared__ float a1[4], a2[4];
    int row = blockIdx.x;
    int tid = threadIdx.x;  // 128
    const float4 v = ((const float4*)(h + (size_t)row * 512))[tid];
    float s1 = v.x + v.y + v.z + v.w;
    float s2 = v.x * v.x + v.y * v.y + v.z * v.z + v.w * v.w;
    #pragma unroll
    for (int o = 16; o; o >>= 1) {
        s1 += __shfl_xor_sync(0xffffffffu, s1, o);
        s2 += __shfl_xor_sync(0xffffffffu, s2, o);
    }
    if ((tid & 31) == 0) { a1[tid >> 5] = s1; a2[tid >> 5] = s2; }
    __syncthreads();
    s1 = a1[0] + a1[1] + a1[2] + a1[3];
    s2 = a2[0] + a2[1] + a2[2] + a2[3];
    float mu  = s1 * (1.0f / 512.0f);
    float var = s2 * (1.0f / 512.0f) - mu * mu;
    float inv = rsqrtf(var + 1e-5f);
    float4 gg = ((const float4*)g)[tid];
    float4 bb = ((const float4*)b)[tid];
    float4 o;
    o.x = (v.x - mu) * inv * gg.x + bb.x;
    o.y = (v.y - mu) * inv * gg.y + bb.y;
    o.z = (v.z - mu) * inv * gg.z + bb.z;
    o.w = (v.w - mu) * inv * gg.w + bb.w;
    ((float4*)(out + (size_t)row * 512))[tid] = o;
}

// ---------------------------------------------------------------------------
extern "C" void kernel_launch(void* const* d_in, const int* in_sizes, int n_in,
                              void* d_out, int out_size)
{
    (void)in_sizes; (void)n_in; (void)out_size;
    const float* x   = (const float*)d_in[0];
    const float* wi  = (const float*)d_in[1];
    const float* cfw = (const float*)d_in[2];
    const float* cfb = (const float*)d_in[3];
    const float* pfw = (const float*)d_in[4];
    const float* pfb = (const float*)d_in[5];
    const float* cbw = (const float*)d_in[6];
    const float* cbb = (const float*)d_in[7];
    const float* pbw = (const float*)d_in[8];
    const float* pbb = (const float*)d_in[9];
    const float* dw  = (const float*)d_in[10];
    const float* gs  = (const float*)d_in[11];
    const float* ow  = (const float*)d_in[12];
    const float* lng = (const float*)d_in[13];
    const float* lnb = (const float*)d_in[14];
    float* out = (float*)d_out;

    unsigned char* S = nullptr;
    cudaGetSymbolAddress((void**)&S, g_scratch);

    __nv_bfloat16* XP  = (__nv_bfloat16*)(S + OB_XP);
    __nv_bfloat16* ZB  = (__nv_bfloat16*)(S + OB_Z);
    __nv_bfloat16* CF  = (__nv_bfloat16*)(S + OB_CF);
    __nv_bfloat16* CB  = (__nv_bfloat16*)(S + OB_CB);
    __nv_bfloat16* YF  = (__nv_bfloat16*)(S + OB_YF);
    __nv_bfloat16* Y2  = (__nv_bfloat16*)(S + OB_Y2);
    __nv_bfloat16* XB  = (__nv_bfloat16*)(S + OB_XB);
    __nv_bfloat16* WIB = (__nv_bfloat16*)(S + OB_WIB);
    __nv_bfloat16* PFB = (__nv_bfloat16*)(S + OB_PFB);
    __nv_bfloat16* PBB = (__nv_bfloat16*)(S + OB_PBB);
    __nv_bfloat16* OWB = (__nv_bfloat16*)(S + OB_OWB);
    float*         H   = (float*)(S + OB_H);

    cudaFuncSetAttribute(gemm_mma, cudaFuncAttributeMaxDynamicSharedMemorySize, 65536);
    const int SMEM = 65536;

    // 0) fp32 -> bf16 staging
    to_bf16<<<16384, 256>>>((const float4*)x,   (uint2*)XB);   // 32768x512
    to_bf16<<<1024, 256>>>((const float4*)wi,   (uint2*)WIB);  // 2048x512
    to_bf16<<<1024, 256>>>((const float4*)pfw,  (uint2*)PFB);  // 1024x1024
    to_bf16<<<1024, 256>>>((const float4*)pbw,  (uint2*)PBB);  // 1024x1024
    to_bf16<<<512,  256>>>((const float4*)ow,   (uint2*)OWB);  // 512x1024

    // 1) xz = x @ in_proj_w^T  -> split XP | Z (bf16)
    gemm_mma<<<dim3(16, 256), 256, SMEM>>>(XB, WIB, XP, ZB, 32768, 2048, 512, 0,
        nullptr, nullptr, nullptr, nullptr, nullptr, nullptr, nullptr);

    // 2) depthwise convs (shift/flip folded) -> bf16
    conv_kernel<<<(32768 * 512) / 256, 256>>>(XP, cfw, cfb, cbw, cbb, CF, CB);

    // 3a) fwd mixer: silu(cf @ Wf^T + b), t==0 masked -> YF
    gemm_mma<<<dim3(8, 256), 256, SMEM>>>(CF, PFB, YF, nullptr, 32768, 1024, 1024, 1,
        pfb, nullptr, nullptr, nullptr, nullptr, nullptr, nullptr);

    // 3b) bwd mixer fused with combine -> Y2
    gemm_mma<<<dim3(8, 256), 256, SMEM>>>(CB, PBB, Y2, nullptr, 32768, 1024, 1024, 4,
        pbb, nullptr, YF, XP, ZB, dw, gs);

    // 4) out_proj + residual -> fp32 H
    gemm_mma<<<dim3(4, 256), 256, SMEM>>>(Y2, OWB, H, nullptr, 32768, 512, 1024, 3,
        nullptr, x, nullptr, nullptr, nullptr, nullptr, nullptr);

    // 5) LayerNorm
    ln_kernel<<<32768, 128>>>(H, lng, lnb, out);
}